// round 2
// baseline (speedup 1.0000x reference)
#include <cuda_runtime.h>
#include <cstdint>

#define E_  64
#define KT_ 4
#define H_  2048
#define I_  1536
#define GS_ 128
#define T_  1024
#define C_  128
#define A_  (T_*KT_)

#define BM 64
#define BN 64
#define BK 32

// ---------- scratch (static device allocations are allowed) ----------
__device__ float d_hbuf[E_*C_*I_];   // expert SwiGLU intermediate  (~48MB)
__device__ float d_shh[T_*I_];       // shared-expert intermediate  (~6MB)
__device__ int   d_topk_idx[A_];
__device__ float d_topk_w[A_];
__device__ int   d_slot_tok[E_*C_];
__device__ float d_slot_w[E_*C_];
__device__ int   d_nrows[E_];

__constant__ float c_lut[16] = {0.0f, 0.5f, 1.0f, 1.5f, 2.0f, 3.0f, 4.0f, 6.0f,
                                -0.0f,-0.5f,-1.0f,-1.5f,-2.0f,-3.0f,-4.0f,-6.0f};

// ---------------- routing: logits -> top4 -> renormalized weights ----------------
__global__ void routing_kernel(const float* __restrict__ x,
                               const float* __restrict__ gw) {
    int t = blockIdx.x;
    __shared__ float xs[H_];
    __shared__ float logits[E_];
    int tid = threadIdx.x;                       // 256 threads
    for (int i = tid; i < H_; i += 256) xs[i] = x[t*H_ + i];
    __syncthreads();
    int warp = tid >> 5, lane = tid & 31;
    for (int e = warp; e < E_; e += 8) {
        const float* w = gw + e*H_;
        float s = 0.f;
        for (int h = lane; h < H_; h += 32) s += xs[h] * w[h];
        #pragma unroll
        for (int o = 16; o; o >>= 1) s += __shfl_down_sync(0xffffffffu, s, o);
        if (lane == 0) logits[e] = s;
    }
    __syncthreads();
    if (tid == 0) {
        int   idx[KT_];
        float val[KT_];
        #pragma unroll
        for (int k = 0; k < KT_; k++) {
            float best = -1e38f; int bi = 0;
            for (int e = 0; e < E_; e++)
                if (logits[e] > best) { best = logits[e]; bi = e; }
            idx[k] = bi; val[k] = best; logits[bi] = -1e38f;
        }
        float m = val[0], sum = 0.f, w[KT_];
        #pragma unroll
        for (int k = 0; k < KT_; k++) { w[k] = expf(val[k] - m); sum += w[k]; }
        #pragma unroll
        for (int k = 0; k < KT_; k++) {
            d_topk_idx[t*KT_ + k] = idx[k];
            d_topk_w  [t*KT_ + k] = w[k] / sum;
        }
    }
}

// ---------------- dispatch: exact assignment-index-order ranks ----------------
__global__ void dispatch_kernel() {
    int e = blockIdx.x;
    int tid = threadIdx.x;                     // 256
    int lane = tid & 31, warp = tid >> 5;
    __shared__ int warp_cnt[8];
    __shared__ int running_s;
    if (tid == 0) running_s = 0;
    __syncthreads();
    for (int base = 0; base < A_; base += 256) {
        int a = base + tid;
        int match = (d_topk_idx[a] == e) ? 1 : 0;
        unsigned bal = __ballot_sync(0xffffffffu, match);
        if (lane == 0) warp_cnt[warp] = __popc(bal);
        __syncthreads();
        int off = running_s;
        for (int wn = 0; wn < warp; wn++) off += warp_cnt[wn];
        int pos = off + __popc(bal & ((1u << lane) - 1));
        if (match && pos < C_) {
            d_slot_tok[e*C_ + pos] = a >> 2;          // a / KT_
            d_slot_w  [e*C_ + pos] = d_topk_w[a];
        }
        __syncthreads();
        if (tid == 0) {
            int tot = 0;
            #pragma unroll
            for (int wn = 0; wn < 8; wn++) tot += warp_cnt[wn];
            running_s += tot;
        }
        __syncthreads();
    }
    if (tid == 0) d_nrows[e] = min(running_s, C_);
}

// ---------------- GEMM1: h = silu(x Wg^T) * (x Wu^T), fused FP4 dequant ----------------
template<bool SHARED>
__global__ void __launch_bounds__(256)
gemm1_kernel(const float* __restrict__ x,
             const int*   __restrict__ gp, const float* __restrict__ gs,
             const int*   __restrict__ up, const float* __restrict__ us) {
    const int e     = SHARED ? 0 : blockIdx.z;
    const int nrows = SHARED ? T_ : d_nrows[e];
    const int m0    = blockIdx.y * BM;
    if (m0 >= nrows) return;
    const int n0 = blockIdx.x * BN;

    const int*   gpk = gp + (SHARED ? 0 : e) * (I_*(H_/8));
    const int*   upk = up + (SHARED ? 0 : e) * (I_*(H_/8));
    const float* gsc = gs + (SHARED ? 0 : e) * ((H_/GS_)*I_);
    const float* usc = us + (SHARED ? 0 : e) * ((H_/GS_)*I_);
    float* outbuf = SHARED ? d_shh : d_hbuf + e*C_*I_;

    __shared__ float a_sh[BK][BM+1];
    __shared__ float bg_sh[BK][BN];
    __shared__ float bu_sh[BK][BN];
    __shared__ float lut_sh[16];
    const int tid = threadIdx.x;
    if (tid < 16) lut_sh[tid] = c_lut[tid];

    // token per A-row handled by this thread
    int tok_r[8];
    #pragma unroll
    for (int i = 0; i < 8; i++) {
        int g = m0 + i*8 + (tid >> 5);
        tok_r[i] = (g < nrows) ? (SHARED ? g : d_slot_tok[e*C_ + g]) : -1;
    }
    __syncthreads();

    float accg[16], accu[16];
    #pragma unroll
    for (int i = 0; i < 16; i++) { accg[i] = 0.f; accu[i] = 0.f; }

    const int col = tid & 31;
    const int o   = tid >> 2;
    const int wi  = tid & 3;
    const int og  = n0 + o;
    const int tx  = tid & 15, ty = tid >> 4;

    for (int kt = 0; kt < H_/BK; kt++) {
        const int h0 = kt * BK;
        // A tile (gathered rows), stored transposed
        #pragma unroll
        for (int i = 0; i < 8; i++) {
            int rl = i*8 + (tid >> 5);
            float v = (tok_r[i] >= 0) ? x[tok_r[i]*H_ + h0 + col] : 0.f;
            a_sh[col][rl] = v;
        }
        // B tiles: dequant FP4 -> float * scale
        {
            int wg = gpk[og*(H_/8) + (h0 >> 3) + wi];
            int wu = upk[og*(H_/8) + (h0 >> 3) + wi];
            float sg = gsc[(h0/GS_)*I_ + og];
            float su = usc[(h0/GS_)*I_ + og];
            #pragma unroll
            for (int j = 0; j < 8; j++) {
                bg_sh[wi*8 + j][o] = lut_sh[(wg >> (4*j)) & 0xF] * sg;
                bu_sh[wi*8 + j][o] = lut_sh[(wu >> (4*j)) & 0xF] * su;
            }
        }
        __syncthreads();
        #pragma unroll
        for (int kk = 0; kk < BK; kk++) {
            float av[4];
            #pragma unroll
            for (int i = 0; i < 4; i++) av[i] = a_sh[kk][ty*4 + i];
            float4 bg4 = *reinterpret_cast<const float4*>(&bg_sh[kk][tx*4]);
            float4 bu4 = *reinterpret_cast<const float4*>(&bu_sh[kk][tx*4]);
            const float bgv[4] = {bg4.x, bg4.y, bg4.z, bg4.w};
            const float buv[4] = {bu4.x, bu4.y, bu4.z, bu4.w};
            #pragma unroll
            for (int i = 0; i < 4; i++)
                #pragma unroll
                for (int j = 0; j < 4; j++) {
                    accg[i*4 + j] += av[i] * bgv[j];
                    accu[i*4 + j] += av[i] * buv[j];
                }
        }
        __syncthreads();
    }
    // SwiGLU epilogue
    #pragma unroll
    for (int i = 0; i < 4; i++) {
        int r = m0 + ty*4 + i;
        if (r < nrows) {
            #pragma unroll
            for (int j = 0; j < 4; j++) {
                int c = n0 + tx*4 + j;
                float g = accg[i*4 + j], u = accu[i*4 + j];
                float hval = g * u / (1.f + expf(-g));
                outbuf[r*I_ + c] = hval;
            }
        }
    }
}

// ---------------- GEMM2: y += weight * (h Wd^T), fused dequant, atomic combine ----------------
template<bool SHARED>
__global__ void __launch_bounds__(256)
gemm2_kernel(const int* __restrict__ dp, const float* __restrict__ ds,
             float* __restrict__ y) {
    const int e     = SHARED ? 0 : blockIdx.z;
    const int nrows = SHARED ? T_ : d_nrows[e];
    const int m0    = blockIdx.y * BM;
    if (m0 >= nrows) return;
    const int n0 = blockIdx.x * BN;

    const float* Ab  = SHARED ? d_shh : d_hbuf + e*C_*I_;
    const int*   dpk = dp + (SHARED ? 0 : e) * (H_*(I_/8));
    const float* dsc = ds + (SHARED ? 0 : e) * ((I_/GS_)*H_);

    __shared__ float a_sh[BK][BM+1];
    __shared__ float b_sh[BK][BN];
    __shared__ float lut_sh[16];
    const int tid = threadIdx.x;
    if (tid < 16) lut_sh[tid] = c_lut[tid];
    __syncthreads();

    float acc[16];
    #pragma unroll
    for (int i = 0; i < 16; i++) acc[i] = 0.f;

    const int col = tid & 31;
    const int o   = tid >> 2;
    const int wi  = tid & 3;
    const int og  = n0 + o;
    const int tx  = tid & 15, ty = tid >> 4;

    for (int kt = 0; kt < I_/BK; kt++) {
        const int i0 = kt * BK;
        #pragma unroll
        for (int i = 0; i < 8; i++) {
            int rl = i*8 + (tid >> 5);
            int g  = m0 + rl;
            float v = (g < nrows) ? Ab[g*I_ + i0 + col] : 0.f;
            a_sh[col][rl] = v;
        }
        {
            int wd = dpk[og*(I_/8) + (i0 >> 3) + wi];
            float sd = dsc[(i0/GS_)*H_ + og];
            #pragma unroll
            for (int j = 0; j < 8; j++)
                b_sh[wi*8 + j][o] = lut_sh[(wd >> (4*j)) & 0xF] * sd;
        }
        __syncthreads();
        #pragma unroll
        for (int kk = 0; kk < BK; kk++) {
            float av[4];
            #pragma unroll
            for (int i = 0; i < 4; i++) av[i] = a_sh[kk][ty*4 + i];
            float4 b4 = *reinterpret_cast<const float4*>(&b_sh[kk][tx*4]);
            const float bv[4] = {b4.x, b4.y, b4.z, b4.w};
            #pragma unroll
            for (int i = 0; i < 4; i++)
                #pragma unroll
                for (int j = 0; j < 4; j++)
                    acc[i*4 + j] += av[i] * bv[j];
        }
        __syncthreads();
    }
    #pragma unroll
    for (int i = 0; i < 4; i++) {
        int r = m0 + ty*4 + i;
        if (r < nrows) {
            int   tok = SHARED ? r   : d_slot_tok[e*C_ + r];
            float w   = SHARED ? 1.f : d_slot_w[e*C_ + r];
            #pragma unroll
            for (int j = 0; j < 4; j++) {
                int c = n0 + tx*4 + j;
                atomicAdd(&y[tok*H_ + c], acc[i*4 + j] * w);
            }
        }
    }
}

extern "C" void kernel_launch(void* const* d_in, const int* in_sizes, int n_in,
                              void* d_out, int out_size) {
    (void)in_sizes; (void)n_in; (void)out_size;
    const float* x    = (const float*)d_in[0];
    const float* gw   = (const float*)d_in[1];
    const float* gsc  = (const float*)d_in[2];
    const float* usc  = (const float*)d_in[3];
    const float* dsc  = (const float*)d_in[4];
    const float* sgsc = (const float*)d_in[5];
    const float* susc = (const float*)d_in[6];
    const float* sdsc = (const float*)d_in[7];
    const int*   gpk  = (const int*)d_in[8];
    const int*   upk  = (const int*)d_in[9];
    const int*   dpk  = (const int*)d_in[10];
    const int*   sgpk = (const int*)d_in[11];
    const int*   supk = (const int*)d_in[12];
    const int*   sdpk = (const int*)d_in[13];
    float* y = (float*)d_out;

    cudaMemsetAsync(y, 0, (size_t)T_ * H_ * sizeof(float), 0);

    routing_kernel<<<T_, 256>>>(x, gw);
    dispatch_kernel<<<E_, 256>>>();

    // expert gate/up + SwiGLU
    {
        dim3 g(I_/BN, C_/BM, E_);
        gemm1_kernel<false><<<g, 256>>>(x, gpk, gsc, upk, usc);
    }
    // shared expert gate/up + SwiGLU
    {
        dim3 g(I_/BN, T_/BM, 1);
        gemm1_kernel<true><<<g, 256>>>(x, sgpk, sgsc, supk, susc);
    }
    // expert down + weighted combine
    {
        dim3 g(H_/BN, C_/BM, E_);
        gemm2_kernel<false><<<g, 256>>>(dpk, dsc, y);
    }
    // shared expert down
    {
        dim3 g(H_/BN, T_/BM, 1);
        gemm2_kernel<true><<<g, 256>>>(sdpk, sdsc, y);
    }
}

// round 4
// speedup vs baseline: 4.0322x; 4.0322x over previous
#include <cuda_runtime.h>
#include <cuda_fp16.h>
#include <cstdint>

#define E_  64
#define KT_ 4
#define H_  2048
#define I_  1536
#define GS_ 128
#define T_  1024
#define C_  128
#define A_  (T_*KT_)

// ---------------- static scratch ----------------
__device__ __align__(16) __half d_xh[T_*H_];        // x in fp16
__device__ __align__(16) __half d_hbuf[E_*C_*I_];   // expert SwiGLU intermediate (fp16)
__device__ __align__(16) __half d_shh[T_*I_];       // shared-expert intermediate (fp16)
__device__ int   d_topk_idx[A_];
__device__ float d_topk_w[A_];
__device__ int   d_slot_tok[E_*C_];
__device__ float d_slot_w[E_*C_];
__device__ int   d_nrows[E_];

__constant__ float c_lut[16] = {0.0f, 0.5f, 1.0f, 1.5f, 2.0f, 3.0f, 4.0f, 6.0f,
                                -0.0f,-0.5f,-1.0f,-1.5f,-2.0f,-3.0f,-4.0f,-6.0f};

// ---------------- helpers ----------------
__device__ __forceinline__ uint32_t smem_u32(const void* p) {
    uint32_t a;
    asm("{ .reg .u64 t; cvta.to.shared.u64 t, %1; cvt.u32.u64 %0, t; }" : "=r"(a) : "l"(p));
    return a;
}

__device__ __forceinline__ void ldsm_x4(uint32_t addr, uint32_t r[4]) {
    asm volatile("ldmatrix.sync.aligned.m8n8.x4.shared.b16 {%0,%1,%2,%3}, [%4];"
        : "=r"(r[0]), "=r"(r[1]), "=r"(r[2]), "=r"(r[3]) : "r"(addr));
}
__device__ __forceinline__ void ldsm_x2(uint32_t addr, uint32_t r[2]) {
    asm volatile("ldmatrix.sync.aligned.m8n8.x2.shared.b16 {%0,%1}, [%2];"
        : "=r"(r[0]), "=r"(r[1]) : "r"(addr));
}
__device__ __forceinline__ void mma16816(float c[4], const uint32_t a[4], const uint32_t b[2]) {
    asm volatile("mma.sync.aligned.m16n8k16.row.col.f32.f16.f16.f32 "
        "{%0,%1,%2,%3}, {%4,%5,%6,%7}, {%8,%9}, {%0,%1,%2,%3};"
        : "+f"(c[0]), "+f"(c[1]), "+f"(c[2]), "+f"(c[3])
        : "r"(a[0]), "r"(a[1]), "r"(a[2]), "r"(a[3]), "r"(b[0]), "r"(b[1]));
}

__device__ __forceinline__ uint4 dq_word(uint32_t w, const uint32_t* lut, __half2 s2) {
    __half2 q0 = __hmul2(*(const __half2*)&lut[w & 255], s2);
    __half2 q1 = __hmul2(*(const __half2*)&lut[(w >> 8) & 255], s2);
    __half2 q2 = __hmul2(*(const __half2*)&lut[(w >> 16) & 255], s2);
    __half2 q3 = __hmul2(*(const __half2*)&lut[w >> 24], s2);
    uint4 o;
    o.x = *(uint32_t*)&q0; o.y = *(uint32_t*)&q1;
    o.z = *(uint32_t*)&q2; o.w = *(uint32_t*)&q3;
    return o;
}

// smem geometry: padded rows, 64 halfs data + 8 pad = 144 bytes/row
#define ROWB 144
#define BUFB (128*ROWB)          // 18432 bytes per buffer
#define XA0  1024                // after 256-entry LUT (1024 B)
#define BG0  (XA0 + 2*BUFB)      // 37888
#define BU0  (BG0 + 2*BUFB)      // 74752
#define SM1_TOTAL (BU0 + 2*BUFB) // 111616
#define SM2_TOTAL (BG0 + 2*BUFB) // 74752 (gemm2: XA + single B at BG0)

// ---------------- x -> fp16 ----------------
__global__ void cvt_x_kernel(const float* __restrict__ x) {
    int i = (blockIdx.x * 256 + threadIdx.x) * 8;
    float4 a = *(const float4*)(x + i);
    float4 b = *(const float4*)(x + i + 4);
    __half2 h0 = __floats2half2_rn(a.x, a.y), h1 = __floats2half2_rn(a.z, a.w);
    __half2 h2 = __floats2half2_rn(b.x, b.y), h3 = __floats2half2_rn(b.z, b.w);
    uint4 o;
    o.x = *(uint32_t*)&h0; o.y = *(uint32_t*)&h1;
    o.z = *(uint32_t*)&h2; o.w = *(uint32_t*)&h3;
    *(uint4*)(d_xh + i) = o;
}

// ---------------- routing ----------------
__global__ void routing_kernel(const float* __restrict__ x,
                               const float* __restrict__ gw) {
    int t = blockIdx.x;
    __shared__ float xs[H_];
    __shared__ float logits[E_];
    int tid = threadIdx.x;
    for (int i = tid; i < H_; i += 256) xs[i] = x[t*H_ + i];
    __syncthreads();
    int warp = tid >> 5, lane = tid & 31;
    for (int e = warp; e < E_; e += 8) {
        const float* w = gw + e*H_;
        float s = 0.f;
        for (int h = lane; h < H_; h += 32) s += xs[h] * w[h];
        #pragma unroll
        for (int o = 16; o; o >>= 1) s += __shfl_down_sync(0xffffffffu, s, o);
        if (lane == 0) logits[e] = s;
    }
    __syncthreads();
    if (tid == 0) {
        int   idx[KT_];
        float val[KT_];
        #pragma unroll
        for (int k = 0; k < KT_; k++) {
            float best = -1e38f; int bi = 0;
            for (int e = 0; e < E_; e++)
                if (logits[e] > best) { best = logits[e]; bi = e; }
            idx[k] = bi; val[k] = best; logits[bi] = -1e38f;
        }
        float m = val[0], sum = 0.f, w[KT_];
        #pragma unroll
        for (int k = 0; k < KT_; k++) { w[k] = expf(val[k] - m); sum += w[k]; }
        #pragma unroll
        for (int k = 0; k < KT_; k++) {
            d_topk_idx[t*KT_ + k] = idx[k];
            d_topk_w  [t*KT_ + k] = w[k] / sum;
        }
    }
}

// ---------------- dispatch ----------------
__global__ void dispatch_kernel() {
    int e = blockIdx.x;
    int tid = threadIdx.x;
    int lane = tid & 31, warp = tid >> 5;
    __shared__ int warp_cnt[8];
    __shared__ int running_s;
    if (tid == 0) running_s = 0;
    __syncthreads();
    for (int base = 0; base < A_; base += 256) {
        int a = base + tid;
        int match = (d_topk_idx[a] == e) ? 1 : 0;
        unsigned bal = __ballot_sync(0xffffffffu, match);
        if (lane == 0) warp_cnt[warp] = __popc(bal);
        __syncthreads();
        int off = running_s;
        for (int wn = 0; wn < warp; wn++) off += warp_cnt[wn];
        int pos = off + __popc(bal & ((1u << lane) - 1));
        if (match && pos < C_) {
            d_slot_tok[e*C_ + pos] = a >> 2;
            d_slot_w  [e*C_ + pos] = d_topk_w[a];
        }
        __syncthreads();
        if (tid == 0) {
            int tot = 0;
            #pragma unroll
            for (int wn = 0; wn < 8; wn++) tot += warp_cnt[wn];
            running_s += tot;
        }
        __syncthreads();
    }
    if (tid == 0) d_nrows[e] = min(running_s, C_);
}

// ---------------- GEMM1 (gate+up + SwiGLU) via mma.sync ----------------
// mma A = activations [tok][k] (row-major), mma B = weights [out][k].
template<bool SHARED>
__global__ void __launch_bounds__(256, 1)
hmma_gemm1(const int* __restrict__ gp, const float* __restrict__ gs,
           const int* __restrict__ up, const float* __restrict__ us)
{
    extern __shared__ char smem[];
    const int e     = SHARED ? 0 : blockIdx.z;
    const int nrows = SHARED ? T_ : d_nrows[e];
    if (!SHARED && nrows == 0) return;
    const int m0 = SHARED ? blockIdx.y * 128 : 0;
    const int n0 = blockIdx.x * 128;
    const int tid = threadIdx.x, wid = tid >> 5, lane = tid & 31;
    const uint32_t sb = smem_u32(smem);
    uint32_t* lut = (uint32_t*)smem;

    const int*   gpk = gp + (size_t)(SHARED ? 0 : e) * (I_*(H_/8));
    const int*   upk = up + (size_t)(SHARED ? 0 : e) * (I_*(H_/8));
    const float* gsc = gs + (size_t)(SHARED ? 0 : e) * ((H_/GS_)*I_);
    const float* usc = us + (size_t)(SHARED ? 0 : e) * ((H_/GS_)*I_);
    __half* outb = SHARED ? d_shh : d_hbuf + (size_t)e * C_ * I_;

    {   // byte -> half2 dequant LUT
        __half lo = __float2half_rn(c_lut[tid & 15]);
        __half hi = __float2half_rn(c_lut[tid >> 4]);
        lut[tid] = (uint32_t)__half_as_ushort(lo) | ((uint32_t)__half_as_ushort(hi) << 16);
    }

    // ---- fill-role constants ----
    const int frow = tid >> 1, fseg = tid & 1;
    int atok;
    if (SHARED) atok = m0 + frow;
    else        atok = (frow < nrows) ? d_slot_tok[e*C_ + frow] : -1;
    const int og = n0 + frow;

    // ---- compute-role constants ----
    const int wm = wid & 3, wn = wid >> 2;     // warp tile: tok 32, out 64
    const uint32_t a_lane = sb + XA0 + (uint32_t)((wm*32 + (lane & 15))*ROWB + (lane >> 4)*16);
    const uint32_t b_off  = (uint32_t)((wn*64 + (lane & 7))*ROWB + ((lane >> 3) & 1)*16);
    const uint32_t bg_lane = sb + BG0 + b_off;
    const uint32_t bu_lane = sb + BU0 + b_off;

    float accg[2][8][4], accu[2][8][4];
    #pragma unroll
    for (int mt = 0; mt < 2; mt++)
        #pragma unroll
        for (int nt = 0; nt < 8; nt++)
            #pragma unroll
            for (int q = 0; q < 4; q++) { accg[mt][nt][q] = 0.f; accu[mt][nt][q] = 0.f; }

    uint4 a4[4], gw4, uw4;
    float gsv, usv;

    // prologue: LDG chunk0, STS into buf0
    {
        if (atok >= 0) {
            const uint4* s = (const uint4*)(d_xh + (size_t)atok*H_ + fseg*32);
            #pragma unroll
            for (int q = 0; q < 4; q++) a4[q] = s[q];
        } else {
            #pragma unroll
            for (int q = 0; q < 4; q++) a4[q] = make_uint4(0,0,0,0);
        }
        gw4 = *(const uint4*)(gpk + og*(H_/8) + fseg*4);
        uw4 = *(const uint4*)(upk + og*(H_/8) + fseg*4);
        gsv = gsc[og]; usv = usc[og];
    }
    __syncthreads();   // LUT ready
    {
        char* xab = smem + XA0;
        #pragma unroll
        for (int q = 0; q < 4; q++)
            *(uint4*)(xab + frow*ROWB + fseg*64 + q*16) = a4[q];
        __half2 sg2 = __half2half2(__float2half_rn(gsv));
        __half2 su2 = __half2half2(__float2half_rn(usv));
        uint32_t gw_[4] = {gw4.x, gw4.y, gw4.z, gw4.w};
        uint32_t uw_[4] = {uw4.x, uw4.y, uw4.z, uw4.w};
        char* gb = smem + BG0;
        char* ub = smem + BU0;
        #pragma unroll
        for (int j = 0; j < 4; j++) {
            *(uint4*)(gb + frow*ROWB + (fseg*4 + j)*16) = dq_word(gw_[j], lut, sg2);
            *(uint4*)(ub + frow*ROWB + (fseg*4 + j)*16) = dq_word(uw_[j], lut, su2);
        }
    }
    __syncthreads();

    const int NC = H_ / 64;
    for (int c = 0; c < NC; c++) {
        const int p = c & 1;
        const bool has_next = (c + 1 < NC);
        // ---- LDG next chunk (early issue) ----
        if (has_next) {
            const int cn = c + 1;
            if (atok >= 0) {
                const uint4* s = (const uint4*)(d_xh + (size_t)atok*H_ + cn*64 + fseg*32);
                #pragma unroll
                for (int q = 0; q < 4; q++) a4[q] = s[q];
            }
            gw4 = *(const uint4*)(gpk + og*(H_/8) + cn*8 + fseg*4);
            uw4 = *(const uint4*)(upk + og*(H_/8) + cn*8 + fseg*4);
            gsv = gsc[(cn >> 1)*I_ + og]; usv = usc[(cn >> 1)*I_ + og];
        }
        // ---- compute on buffer p ----
        {
            const uint32_t ab = a_lane + p*BUFB;
            const uint32_t gbl = bg_lane + p*BUFB;
            const uint32_t ubl = bu_lane + p*BUFB;
            #pragma unroll
            for (int ks = 0; ks < 4; ks++) {
                uint32_t af[2][4];
                ldsm_x4(ab + 0*16*ROWB + ks*32, af[0]);
                ldsm_x4(ab + 1*16*ROWB + ks*32, af[1]);
                #pragma unroll
                for (int nt = 0; nt < 8; nt++) {
                    uint32_t bgf[2], buf_[2];
                    ldsm_x2(gbl + nt*8*ROWB + ks*32, bgf);
                    ldsm_x2(ubl + nt*8*ROWB + ks*32, buf_);
                    mma16816(accg[0][nt], af[0], bgf);
                    mma16816(accg[1][nt], af[1], bgf);
                    mma16816(accu[0][nt], af[0], buf_);
                    mma16816(accu[1][nt], af[1], buf_);
                }
            }
        }
        // ---- STS next into buffer p^1 ----
        if (has_next) {
            char* xab = smem + XA0 + (p^1)*BUFB;
            #pragma unroll
            for (int q = 0; q < 4; q++)
                *(uint4*)(xab + frow*ROWB + fseg*64 + q*16) = a4[q];
            __half2 sg2 = __half2half2(__float2half_rn(gsv));
            __half2 su2 = __half2half2(__float2half_rn(usv));
            uint32_t gw_[4] = {gw4.x, gw4.y, gw4.z, gw4.w};
            uint32_t uw_[4] = {uw4.x, uw4.y, uw4.z, uw4.w};
            char* gb = smem + BG0 + (p^1)*BUFB;
            char* ub = smem + BU0 + (p^1)*BUFB;
            #pragma unroll
            for (int j = 0; j < 4; j++) {
                *(uint4*)(gb + frow*ROWB + (fseg*4 + j)*16) = dq_word(gw_[j], lut, sg2);
                *(uint4*)(ub + frow*ROWB + (fseg*4 + j)*16) = dq_word(uw_[j], lut, su2);
            }
        }
        __syncthreads();
    }

    // ---- SwiGLU epilogue ----
    const int r0 = wm*32 + (lane >> 2);
    const int c0 = (lane & 3)*2;
    #pragma unroll
    for (int mt = 0; mt < 2; mt++) {
        #pragma unroll
        for (int nt = 0; nt < 8; nt++) {
            int rowA = r0 + mt*16, rowB = rowA + 8;
            int col = n0 + wn*64 + nt*8 + c0;
            float g0 = accg[mt][nt][0], g1 = accg[mt][nt][1];
            float u0 = accu[mt][nt][0], u1 = accu[mt][nt][1];
            float g2 = accg[mt][nt][2], g3 = accg[mt][nt][3];
            float u2 = accu[mt][nt][2], u3 = accu[mt][nt][3];
            float h0 = g0*u0/(1.f+__expf(-g0)), h1 = g1*u1/(1.f+__expf(-g1));
            float h2 = g2*u2/(1.f+__expf(-g2)), h3 = g3*u3/(1.f+__expf(-g3));
            __half2 p01 = __floats2half2_rn(h0, h1);
            __half2 p23 = __floats2half2_rn(h2, h3);
            *(uint32_t*)(outb + (size_t)(m0 + rowA)*I_ + col) = *(uint32_t*)&p01;
            *(uint32_t*)(outb + (size_t)(m0 + rowB)*I_ + col) = *(uint32_t*)&p23;
        }
    }
}

// ---------------- GEMM2 (down + weighted combine) via mma.sync ----------------
template<bool SHARED>
__global__ void __launch_bounds__(256, 1)
hmma_gemm2(const int* __restrict__ dp, const float* __restrict__ ds,
           float* __restrict__ y)
{
    extern __shared__ char smem[];
    const int e     = SHARED ? 0 : blockIdx.z;
    const int nrows = SHARED ? T_ : d_nrows[e];
    if (!SHARED && nrows == 0) return;
    const int m0 = SHARED ? blockIdx.y * 128 : 0;
    const int n0 = blockIdx.x * 128;
    const int tid = threadIdx.x, wid = tid >> 5, lane = tid & 31;
    const uint32_t sb = smem_u32(smem);
    uint32_t* lut = (uint32_t*)smem;

    const int*   dpk = dp + (size_t)(SHARED ? 0 : e) * (H_*(I_/8));
    const float* dsc = ds + (size_t)(SHARED ? 0 : e) * ((I_/GS_)*H_);
    const __half* hb = SHARED ? d_shh : d_hbuf + (size_t)e * C_ * I_;

    {
        __half lo = __float2half_rn(c_lut[tid & 15]);
        __half hi = __float2half_rn(c_lut[tid >> 4]);
        lut[tid] = (uint32_t)__half_as_ushort(lo) | ((uint32_t)__half_as_ushort(hi) << 16);
    }

    const int frow = tid >> 1, fseg = tid & 1;
    const int og = n0 + frow;

    const int wm = wid & 3, wn = wid >> 2;
    const uint32_t a_lane = sb + XA0 + (uint32_t)((wm*32 + (lane & 15))*ROWB + (lane >> 4)*16);
    const uint32_t b_lane = sb + BG0 + (uint32_t)((wn*64 + (lane & 7))*ROWB + ((lane >> 3) & 1)*16);

    float acc[2][8][4];
    #pragma unroll
    for (int mt = 0; mt < 2; mt++)
        #pragma unroll
        for (int nt = 0; nt < 8; nt++)
            #pragma unroll
            for (int q = 0; q < 4; q++) acc[mt][nt][q] = 0.f;

    uint4 a4[4], dw4;
    float dsv;

    {   // prologue LDG chunk0
        const uint4* s = (const uint4*)(hb + (size_t)(m0 + frow)*I_ + fseg*32);
        #pragma unroll
        for (int q = 0; q < 4; q++) a4[q] = s[q];
        dw4 = *(const uint4*)(dpk + og*(I_/8) + fseg*4);
        dsv = dsc[og];
    }
    __syncthreads();
    {
        char* xab = smem + XA0;
        #pragma unroll
        for (int q = 0; q < 4; q++)
            *(uint4*)(xab + frow*ROWB + fseg*64 + q*16) = a4[q];
        __half2 s2 = __half2half2(__float2half_rn(dsv));
        uint32_t dw_[4] = {dw4.x, dw4.y, dw4.z, dw4.w};
        char* bb = smem + BG0;
        #pragma unroll
        for (int j = 0; j < 4; j++)
            *(uint4*)(bb + frow*ROWB + (fseg*4 + j)*16) = dq_word(dw_[j], lut, s2);
    }
    __syncthreads();

    const int NC = I_ / 64;
    for (int c = 0; c < NC; c++) {
        const int p = c & 1;
        const bool has_next = (c + 1 < NC);
        if (has_next) {
            const int cn = c + 1;
            const uint4* s = (const uint4*)(hb + (size_t)(m0 + frow)*I_ + cn*64 + fseg*32);
            #pragma unroll
            for (int q = 0; q < 4; q++) a4[q] = s[q];
            dw4 = *(const uint4*)(dpk + og*(I_/8) + cn*8 + fseg*4);
            dsv = dsc[(cn >> 1)*H_ + og];
        }
        {
            const uint32_t ab = a_lane + p*BUFB;
            const uint32_t bb = b_lane + p*BUFB;
            #pragma unroll
            for (int ks = 0; ks < 4; ks++) {
                uint32_t af[2][4];
                ldsm_x4(ab + 0*16*ROWB + ks*32, af[0]);
                ldsm_x4(ab + 1*16*ROWB + ks*32, af[1]);
                #pragma unroll
                for (int nt = 0; nt < 8; nt++) {
                    uint32_t bf[2];
                    ldsm_x2(bb + nt*8*ROWB + ks*32, bf);
                    mma16816(acc[0][nt], af[0], bf);
                    mma16816(acc[1][nt], af[1], bf);
                }
            }
        }
        if (has_next) {
            char* xab = smem + XA0 + (p^1)*BUFB;
            #pragma unroll
            for (int q = 0; q < 4; q++)
                *(uint4*)(xab + frow*ROWB + fseg*64 + q*16) = a4[q];
            __half2 s2 = __half2half2(__float2half_rn(dsv));
            uint32_t dw_[4] = {dw4.x, dw4.y, dw4.z, dw4.w};
            char* bb = smem + BG0 + (p^1)*BUFB;
            #pragma unroll
            for (int j = 0; j < 4; j++)
                *(uint4*)(bb + frow*ROWB + (fseg*4 + j)*16) = dq_word(dw_[j], lut, s2);
        }
        __syncthreads();
    }

    // ---- combine epilogue ----
    const int r0 = wm*32 + (lane >> 2);
    const int c0 = (lane & 3)*2;
    #pragma unroll
    for (int mt = 0; mt < 2; mt++) {
        int rowA = r0 + mt*16, rowB = rowA + 8;
        int tokA = -1, tokB = -1; float wA = 0.f, wB = 0.f;
        if (SHARED) { tokA = m0 + rowA; tokB = m0 + rowB; wA = wB = 1.f; }
        else {
            if (rowA < nrows) { tokA = d_slot_tok[e*C_ + rowA]; wA = d_slot_w[e*C_ + rowA]; }
            if (rowB < nrows) { tokB = d_slot_tok[e*C_ + rowB]; wB = d_slot_w[e*C_ + rowB]; }
        }
        #pragma unroll
        for (int nt = 0; nt < 8; nt++) {
            int col = n0 + wn*64 + nt*8 + c0;
            if (tokA >= 0) {
                atomicAdd(y + (size_t)tokA*H_ + col,     acc[mt][nt][0]*wA);
                atomicAdd(y + (size_t)tokA*H_ + col + 1, acc[mt][nt][1]*wA);
            }
            if (tokB >= 0) {
                atomicAdd(y + (size_t)tokB*H_ + col,     acc[mt][nt][2]*wB);
                atomicAdd(y + (size_t)tokB*H_ + col + 1, acc[mt][nt][3]*wB);
            }
        }
    }
}

// ---------------- launch ----------------
extern "C" void kernel_launch(void* const* d_in, const int* in_sizes, int n_in,
                              void* d_out, int out_size) {
    (void)in_sizes; (void)n_in; (void)out_size;
    const float* x    = (const float*)d_in[0];
    const float* gw   = (const float*)d_in[1];
    const float* gsc  = (const float*)d_in[2];
    const float* usc  = (const float*)d_in[3];
    const float* dsc  = (const float*)d_in[4];
    const float* sgsc = (const float*)d_in[5];
    const float* susc = (const float*)d_in[6];
    const float* sdsc = (const float*)d_in[7];
    const int*   gpk  = (const int*)d_in[8];
    const int*   upk  = (const int*)d_in[9];
    const int*   dpk  = (const int*)d_in[10];
    const int*   sgpk = (const int*)d_in[11];
    const int*   supk = (const int*)d_in[12];
    const int*   sdpk = (const int*)d_in[13];
    float* y = (float*)d_out;

    cudaFuncSetAttribute(hmma_gemm1<false>, cudaFuncAttributeMaxDynamicSharedMemorySize, SM1_TOTAL);
    cudaFuncSetAttribute(hmma_gemm1<true>,  cudaFuncAttributeMaxDynamicSharedMemorySize, SM1_TOTAL);
    cudaFuncSetAttribute(hmma_gemm2<false>, cudaFuncAttributeMaxDynamicSharedMemorySize, SM2_TOTAL);
    cudaFuncSetAttribute(hmma_gemm2<true>,  cudaFuncAttributeMaxDynamicSharedMemorySize, SM2_TOTAL);

    cudaMemsetAsync(y, 0, (size_t)T_ * H_ * sizeof(float), 0);
    cvt_x_kernel<<<(T_*H_)/2048, 256>>>(x);
    routing_kernel<<<T_, 256>>>(x, gw);
    dispatch_kernel<<<E_, 256>>>();

    { dim3 g(I_/128, 1, E_);     hmma_gemm1<false><<<g, 256, SM1_TOTAL>>>(gpk, gsc, upk, usc); }
    { dim3 g(I_/128, T_/128, 1); hmma_gemm1<true><<<g, 256, SM1_TOTAL>>>(sgpk, sgsc, supk, susc); }
    { dim3 g(H_/128, 1, E_);     hmma_gemm2<false><<<g, 256, SM2_TOTAL>>>(dpk, dsc, y); }
    { dim3 g(H_/128, T_/128, 1); hmma_gemm2<true><<<g, 256, SM2_TOTAL>>>(sdpk, sdsc, y); }
}